// round 17
// baseline (speedup 1.0000x reference)
#include <cuda_runtime.h>
#include <math.h>
#include <stdint.h>

#define S_LEN 4096
#define DM    1024
#define NH    16
#define NKV   4
#define HD    64
#define KV_W  256
#define KROWW 36
#define KBLKW (64*KROWW)          // 2304 words (attention K tile)
#define VBLKW 2048                // attention V tile: 64 LDSM matrices
#define KVBLKW (KBLKW+VBLKW)      // 4352 words = 17408 B
#define NSPLIT 2
#define TILES_PER_SPLIT 32

#define QSC   0.1803368801111204f     // (1/8) * log2(e)
#define EOFF  5.770780163555852f      // 4 * log2(e)
#define RFREQ -0.41524101187353416f   // -log2(10000)/32

#define GSTG  (256*20 + 1024)     // 6144 words per GEMM stage

// Scratch (allocation-free rule)
__device__ uint32_t g_q16 [S_LEN*DM/2];      // fp16x2 rope'd+scaled Q
__device__ uint32_t g_x16 [S_LEN*DM/2];      // fp16x2 x
__device__ uint32_t g_ao16[S_LEN*DM/2];      // fp16x2 attention out
__device__ uint32_t g_wq16[DM/2*DM];         // weights, LDSM-tiled
__device__ uint32_t g_wk16[DM/2*KV_W];
__device__ uint32_t g_wv16[DM/2*KV_W];
__device__ uint32_t g_wo16[DM/2*DM];
__device__ uint32_t g_KV16[NKV*64*KVBLKW];   // fp16 K/V tile blocks
__device__ float    g_pO  [NSPLIT*S_LEN*DM]; // split-KV partial O (fp32)
__device__ float    g_pl  [NSPLIT*S_LEN*NH]; // split-KV partial l
__device__ int      g_ctr [ (S_LEN/128)*NH ];// split-KV semaphores (512)

// ---- fp16 helpers ----
__device__ __forceinline__ uint32_t h2pack(float lo, float hi) {
    uint32_t d; asm("cvt.rn.f16x2.f32 %0, %1, %2;" : "=r"(d) : "f"(hi), "f"(lo)); return d;
}
__device__ __forceinline__ uint32_t hex2(uint32_t x) {
    uint32_t y; asm("ex2.approx.f16x2 %0, %1;" : "=r"(y) : "r"(x)); return y;
}
__device__ __forceinline__ void hmma16(float* d, uint32_t a0, uint32_t a1,
                                       uint32_t a2, uint32_t a3,
                                       uint32_t b0, uint32_t b1) {
    asm volatile(
        "mma.sync.aligned.m16n8k16.row.col.f32.f16.f16.f32 "
        "{%0,%1,%2,%3},{%4,%5,%6,%7},{%8,%9},{%0,%1,%2,%3};"
        : "+f"(d[0]), "+f"(d[1]), "+f"(d[2]), "+f"(d[3])
        : "r"(a0), "r"(a1), "r"(a2), "r"(a3), "r"(b0), "r"(b1));
}
__device__ __forceinline__ void ldsm4(uint32_t& r0, uint32_t& r1, uint32_t& r2,
                                      uint32_t& r3, uint32_t addr) {
    asm volatile("ldmatrix.sync.aligned.m8n8.x4.shared.b16 {%0,%1,%2,%3}, [%4];"
        : "=r"(r0), "=r"(r1), "=r"(r2), "=r"(r3) : "r"(addr));
}
__device__ __forceinline__ uint32_t smem_u32(const void* p){
    uint32_t a;
    asm("{ .reg .u64 t; cvta.to.shared.u64 t, %1; cvt.u32.u64 %0, t; }" : "=r"(a) : "l"(p));
    return a;
}

// ---------------------------------------------------------------------------
// Conversions: x -> fp16x2 pairs; weights -> LDSM-tiled blocks; ctr reset.
// ---------------------------------------------------------------------------
__device__ __forceinline__ void wtile_one(const float* __restrict__ w,
                                          uint32_t* __restrict__ wp, int N, int i) {
    int n4c = N >> 2;
    int k2 = i / n4c, n4 = (i - k2*n4c) << 2;
    int k  = 2*k2;
    int ch = k >> 5, kc = k & 31;
    int s = kc >> 4, hh = (kc >> 3) & 1, ww = (kc & 7) >> 1;
    int nb = n4 >> 6, nl = n4 & 63;
    int ng = nl >> 3, rr = nl & 7;
    float4 r0 = *(const float4*)&w[(size_t)k      *N + n4];
    float4 r1 = *(const float4*)&w[(size_t)(k + 1)*N + n4];
    uint32_t* base = wp + ((size_t)(nb*32 + ch)*32 + (s*8 + ng)*2 + hh)*32 + ww;
    base[(rr    )*4] = h2pack(r0.x, r1.x);
    base[(rr + 1)*4] = h2pack(r0.y, r1.y);
    base[(rr + 2)*4] = h2pack(r0.z, r1.z);
    base[(rr + 3)*4] = h2pack(r0.w, r1.w);
}

__global__ void cvt_all(const float* __restrict__ x,
                        const float* __restrict__ w_q, const float* __restrict__ w_k,
                        const float* __restrict__ w_v, const float* __restrict__ w_o) {
    int i = blockIdx.x * blockDim.x + threadIdx.x;
    const int NX  = S_LEN*DM/8;
    const int NWQ = (DM/2)*(DM/4);
    const int NWK = (DM/2)*(KV_W/4);
    if (i < NX) {
        float4 a = ((const float4*)x)[2*i];
        float4 b = ((const float4*)x)[2*i + 1];
        ((uint4*)g_x16)[i] = make_uint4(h2pack(a.x, a.y), h2pack(a.z, a.w),
                                        h2pack(b.x, b.y), h2pack(b.z, b.w));
        return;
    }
    i -= NX;
    if (i < NWQ) { wtile_one(w_q, g_wq16, DM, i); return; }
    i -= NWQ;
    if (i < NWK) { wtile_one(w_k, g_wk16, KV_W, i); return; }
    i -= NWK;
    if (i < NWK) { wtile_one(w_v, g_wv16, KV_W, i); return; }
    i -= NWK;
    if (i < NWQ) { wtile_one(w_o, g_wo16, DM, i); return; }
    i -= NWQ;
    if (i < (S_LEN/128)*NH) g_ctr[i] = 0;   // reset split-KV semaphores
}

// ---------------------------------------------------------------------------
// GEMM mainloop: 256x64 CTA tile, LDSM fragments, triple-buffer single-sync.
// ---------------------------------------------------------------------------
__device__ __forceinline__ void gemm16_core(const uint32_t* __restrict__ A, int aStrW,
                                            const uint32_t* __restrict__ Bt,
                                            int row0, uint32_t* smg,
                                            float acc[2][8][4]) {
    const int tid = threadIdx.x;
    const int w = tid >> 5, l = tid & 31;
    const int mat = l >> 3, rowsel = l & 7;
    const uint32_t sb = smem_u32(smg);
    const uint32_t offA = (uint32_t)(((w*32 + (mat & 1)*8 + rowsel)*20 + (mat >> 1)*4)*4);
    const uint32_t offB = (uint32_t)(mat*128 + rowsel*16);

    #define GISSUE(c, st) do {                                                     \
        const int _c = (c);                                                        \
        uint32_t _ab = sb + (st)*GSTG*4;                                           \
        _Pragma("unroll")                                                          \
        for (int _i = 0; _i < 4; _i++) {                                           \
            int _u = tid + (_i << 8);                                              \
            int _r = _u >> 2, _f = (_u & 3) << 2;                                  \
            asm volatile("cp.async.cg.shared.global [%0], [%1], 16;"               \
                :: "r"(_ab + (_r*20 + _f)*4),                                      \
                   "l"(&A[(size_t)(row0 + _r)*aStrW + _c*16 + _f]) : "memory");    \
        }                                                                          \
        asm volatile("cp.async.cg.shared.global [%0], [%1], 16;"                   \
            :: "r"(_ab + 256*20*4 + tid*16), "l"(Bt + _c*1024 + tid*4) : "memory");\
        asm volatile("cp.async.commit_group;" ::: "memory");                       \
    } while (0)

    GISSUE(0, 0);
    int bc = 0;
    for (int c = 0; c < 32; c++) {
        int bn = (bc == 2) ? 0 : bc + 1;
        if (c < 31) {
            GISSUE(c + 1, bn);
            asm volatile("cp.async.wait_group 1;" ::: "memory");
        } else {
            asm volatile("cp.async.wait_group 0;" ::: "memory");
        }
        __syncthreads();
        const uint32_t Ab = sb + bc*GSTG*4;
        const uint32_t Bb = Ab + 256*20*4;
        #pragma unroll
        for (int s = 0; s < 2; s++) {
            uint32_t a[2][4];
            ldsm4(a[0][0], a[0][1], a[0][2], a[0][3], Ab + offA + s*32);
            ldsm4(a[1][0], a[1][1], a[1][2], a[1][3], Ab + offA + 16*20*4 + s*32);
            #pragma unroll
            for (int np = 0; np < 4; np++) {
                uint32_t b0, b1, b2, b3;
                ldsm4(b0, b1, b2, b3, Bb + (uint32_t)(((s*8 + 2*np)*2)*128) + offB);
                hmma16(acc[0][2*np    ], a[0][0], a[0][1], a[0][2], a[0][3], b0, b1);
                hmma16(acc[1][2*np    ], a[1][0], a[1][1], a[1][2], a[1][3], b0, b1);
                hmma16(acc[0][2*np + 1], a[0][0], a[0][1], a[0][2], a[0][3], b2, b3);
                hmma16(acc[1][2*np + 1], a[1][0], a[1][1], a[1][2], a[1][3], b2, b3);
            }
        }
        bc = bn;
    }
    #undef GISSUE
}

// In-register RoPE on acc (cols 8j+2q pair with +32 = j+4).
__device__ __forceinline__ void rope_acc(float acc[2][8][4], int row0, int w,
                                         int g, int q, const float* invf /*[8]*/) {
    #pragma unroll
    for (int rb = 0; rb < 2; rb++) {
        #pragma unroll
        for (int rr = 0; rr < 2; rr++) {
            int pos = row0 + w*32 + rb*16 + g + rr*8;
            #pragma unroll
            for (int j = 0; j < 4; j++) {
                #pragma unroll
                for (int c01 = 0; c01 < 2; c01++) {
                    float ang = (float)pos * invf[j*2 + c01];
                    float cs, sn;
                    sincosf(ang, &sn, &cs);
                    int e = 2*rr + c01;
                    float v1 = acc[rb][j    ][e];
                    float v2 = acc[rb][j + 4][e];
                    acc[rb][j    ][e] = v1*cs - v2*sn;
                    acc[rb][j + 4][e] = v1*sn + v2*cs;
                }
            }
        }
    }
}

// ---------------------------------------------------------------------------
// Fused Q/K/V projections + RoPE + fp16 repack. grid (24, 16), 256 threads.
// ---------------------------------------------------------------------------
__global__ __launch_bounds__(256) void gemm16_qkv(const uint32_t* __restrict__ x16) {
    extern __shared__ uint32_t smg[];
    const int tid = threadIdx.x;
    const int w = tid >> 5, l = tid & 31, g = l >> 2, q = l & 3;
    const int bx = blockIdx.x, row0 = blockIdx.y << 8;
    float acc[2][8][4] = {};

    if (bx < 16) {
        gemm16_core(x16, DM/2, g_wq16 + (size_t)bx*32768, row0, smg, acc);
        float invf[8];
        #pragma unroll
        for (int j = 0; j < 4; j++) {
            invf[2*j]     = exp2f((float)(8*j + 2*q)     * RFREQ);
            invf[2*j + 1] = exp2f((float)(8*j + 2*q + 1) * RFREQ);
        }
        rope_acc(acc, row0, w, g, q, invf);
        const int h = bx;
        #pragma unroll
        for (int rb = 0; rb < 2; rb++) {
            int rbase = row0 + w*32 + rb*16;
            #pragma unroll
            for (int j = 0; j < 8; j++) {
                g_q16[(size_t)(rbase + g    )*(DM/2) + h*32 + 4*j + q] =
                    h2pack(acc[rb][j][0]*QSC, acc[rb][j][1]*QSC);
                g_q16[(size_t)(rbase + g + 8)*(DM/2) + h*32 + 4*j + q] =
                    h2pack(acc[rb][j][2]*QSC, acc[rb][j][3]*QSC);
            }
        }
    } else if (bx < 20) {
        const int kh = bx - 16;
        gemm16_core(x16, DM/2, g_wk16 + (size_t)kh*32768, row0, smg, acc);
        float invf[8];
        #pragma unroll
        for (int j = 0; j < 4; j++) {
            invf[2*j]     = exp2f((float)(8*j + 2*q)     * RFREQ);
            invf[2*j + 1] = exp2f((float)(8*j + 2*q + 1) * RFREQ);
        }
        rope_acc(acc, row0, w, g, q, invf);
        #pragma unroll
        for (int rb = 0; rb < 2; rb++) {
            #pragma unroll
            for (int rr = 0; rr < 2; rr++) {
                int r = row0 + w*32 + rb*16 + g + rr*8;
                uint32_t* blk = g_KV16 + (size_t)(kh*64 + (r >> 6))*KVBLKW + (r & 63)*KROWW;
                #pragma unroll
                for (int j = 0; j < 8; j++)
                    blk[4*j + q] = h2pack(acc[rb][j][2*rr], acc[rb][j][2*rr + 1]);
            }
        }
    } else {
        const int kh = bx - 20;
        gemm16_core(x16, DM/2, g_wv16 + (size_t)kh*32768, row0, smg, acc);
        #pragma unroll
        for (int rb = 0; rb < 2; rb++) {
            #pragma unroll
            for (int j = 0; j < 8; j++) {
                #pragma unroll
                for (int e = 0; e < 4; e++) {
                    float mine = acc[rb][j][e];
                    float part = __shfl_down_sync(0xffffffffu, mine, 4);
                    if (!(g & 1)) {
                        int rr = e >> 1, c01 = e & 1;
                        int r = row0 + w*32 + rb*16 + g + rr*8;   // even key
                        int tile = r >> 6;
                        int kl2 = (r & 63) >> 1;
                        int jp = kl2 >> 3, kp7 = kl2 & 7;
                        int hh = kp7 >> 2, ww = kp7 & 3;
                        int rmat = 2*q + c01;
                        int word = ((jp*8 + j)*2 + hh)*32 + rmat*4 + ww;
                        g_KV16[(size_t)(kh*64 + tile)*KVBLKW + KBLKW + word] =
                            h2pack(mine, part);
                    }
                }
            }
        }
    }
}

// O-projection.
__global__ __launch_bounds__(256) void gemm16_o(const uint32_t* __restrict__ ao16,
                                                float* __restrict__ out) {
    extern __shared__ uint32_t smg[];
    const int tid = threadIdx.x;
    const int w = tid >> 5, l = tid & 31, g = l >> 2, q = l & 3;
    const int row0 = blockIdx.y << 8, n0 = blockIdx.x << 6;
    float acc[2][8][4] = {};
    gemm16_core(ao16, DM/2, g_wo16 + (size_t)blockIdx.x*32768, row0, smg, acc);
    #pragma unroll
    for (int rb = 0; rb < 2; rb++) {
        int rbase = row0 + w*32 + rb*16;
        #pragma unroll
        for (int j = 0; j < 8; j++) {
            *(float2*)&out[(size_t)(rbase + g    )*DM + n0 + j*8 + 2*q] =
                make_float2(acc[rb][j][0], acc[rb][j][1]);
            *(float2*)&out[(size_t)(rbase + g + 8)*DM + n0 + j*8 + 2*q] =
                make_float2(acc[rb][j][2], acc[rb][j][3]);
        }
    }
}

// ---------------------------------------------------------------------------
// Flash attention, split-KV (2 splits x 32 tiles). Partials are exactly
// additive (static-max softmax): O = O0+O1, l = l0+l1. Second finisher per
// (q-block, head) merges, normalizes, writes fp16 (semaphore pattern).
// Grid (S/128, NH, 2), 128 threads, 3 CTAs/SM.
// ---------------------------------------------------------------------------
__global__ __launch_bounds__(128, 3) void attn16(uint32_t* __restrict__ out) {
    extern __shared__ uint32_t sm[];             // 3 * KVBLKW words
    __shared__ int s_last;
    const int tid = threadIdx.x;
    const int w = tid >> 5, l = tid & 31, g = l >> 2, q = l & 3;
    const int h  = blockIdx.y;
    const int kh = h >> 2;
    const int q0 = blockIdx.x << 7;
    const int sp = blockIdx.z;
    const int t0 = sp*TILES_PER_SPLIT;
    const uint32_t sbase = smem_u32(sm);
    const uint32_t* src = g_KV16 + (size_t)kh*64*KVBLKW;

    const int mat = l >> 3, rowsel = l & 7;
    const uint32_t offk = (uint32_t)(((mat >= 2 ? 8 : 0) + rowsel)*(KROWW*4) + (mat & 1)*16);
    const uint32_t offv = (uint32_t)(mat*128 + rowsel*16);
    const uint32_t ONE2 = (g == 0) ? 0x3C003C00u : 0u;

    uint32_t qf[2][4][4];
    #pragma unroll
    for (int rb = 0; rb < 2; rb++)
        #pragma unroll
        for (int rr = 0; rr < 2; rr++) {
            const uint32_t* qrow = g_q16 +
                (size_t)(q0 + w*32 + rb*16 + g + rr*8)*(DM/2) + h*32;
            #pragma unroll
            for (int sl = 0; sl < 2; sl++)
                #pragma unroll
                for (int hi = 0; hi < 2; hi++) {
                    int wd = 8*sl + q + 16*hi;
                    qf[rb][sl + 2*hi][rr]     = qrow[wd];
                    qf[rb][sl + 2*hi][2 + rr] = qrow[wd + 4];
                }
        }

    float oacc[2][9][4] = {};

    #define ISSUE(t, bi) do {                                                      \
        const uint32_t* _gp = src + (size_t)(t)*KVBLKW;                            \
        uint32_t _sb = sbase + (bi)*KVBLKW*4;                                      \
        _Pragma("unroll")                                                          \
        for (int _i = 0; _i < 9; _i++) {                                           \
            int _idx = tid + (_i << 7);                                            \
            if (_idx < KVBLKW/4)                                                   \
                asm volatile("cp.async.cg.shared.global [%0], [%1], 16;"           \
                    :: "r"(_sb + _idx*16), "l"(_gp + _idx*4) : "memory");          \
        }                                                                          \
        asm volatile("cp.async.commit_group;" ::: "memory");                       \
    } while (0)

    ISSUE(t0, 0);
    int bc = 0;
    for (int t = 0; t < TILES_PER_SPLIT; t++) {
        int bn = (bc == 2) ? 0 : bc + 1;
        if (t < TILES_PER_SPLIT - 1) {
            ISSUE(t0 + t + 1, bn);
            asm volatile("cp.async.wait_group 1;" ::: "memory");
        } else {
            asm volatile("cp.async.wait_group 0;" ::: "memory");
        }
        __syncthreads();
        const uint32_t Kb = sbase + bc*KVBLKW*4;
        const uint32_t Vb = Kb + KBLKW*4;

        #pragma unroll
        for (int jp = 0; jp < 4; jp++) {
            float sfa[2][4], sfb[2][4];
            #pragma unroll
            for (int rb = 0; rb < 2; rb++)
                #pragma unroll
                for (int i = 0; i < 4; i++) { sfa[rb][i] = -EOFF; sfb[rb][i] = -EOFF; }
            #pragma unroll
            for (int s = 0; s < 4; s++) {
                uint32_t b0, b1, c0, c1;
                ldsm4(b0, b1, c0, c1, Kb + (uint32_t)(jp*2304 + s*32) + offk);
                hmma16(sfa[0], qf[0][s][0], qf[0][s][1], qf[0][s][2], qf[0][s][3], b0, b1);
                hmma16(sfa[1], qf[1][s][0], qf[1][s][1], qf[1][s][2], qf[1][s][3], b0, b1);
                hmma16(sfb[0], qf[0][s][0], qf[0][s][1], qf[0][s][2], qf[0][s][3], c0, c1);
                hmma16(sfb[1], qf[1][s][0], qf[1][s][1], qf[1][s][2], qf[1][s][3], c0, c1);
            }
            uint32_t pa[2][4];
            #pragma unroll
            for (int rb = 0; rb < 2; rb++) {
                pa[rb][0] = hex2(h2pack(sfa[rb][0], sfa[rb][1]));
                pa[rb][1] = hex2(h2pack(sfa[rb][2], sfa[rb][3]));
                pa[rb][2] = hex2(h2pack(sfb[rb][0], sfb[rb][1]));
                pa[rb][3] = hex2(h2pack(sfb[rb][2], sfb[rb][3]));
            }
            #pragma unroll
            for (int np = 0; np < 4; np++) {
                uint32_t v0, v1, v2, v3;
                ldsm4(v0, v1, v2, v3, Vb + (uint32_t)((jp*16 + np*4)*128) + offv);
                hmma16(oacc[0][2*np    ], pa[0][0], pa[0][1], pa[0][2], pa[0][3], v0, v1);
                hmma16(oacc[1][2*np    ], pa[1][0], pa[1][1], pa[1][2], pa[1][3], v0, v1);
                hmma16(oacc[0][2*np + 1], pa[0][0], pa[0][1], pa[0][2], pa[0][3], v2, v3);
                hmma16(oacc[1][2*np + 1], pa[1][0], pa[1][1], pa[1][2], pa[1][3], v2, v3);
            }
            hmma16(oacc[0][8], pa[0][0], pa[0][1], pa[0][2], pa[0][3], ONE2, ONE2);
            hmma16(oacc[1][8], pa[1][0], pa[1][1], pa[1][2], pa[1][3], ONE2, ONE2);
        }
        bc = bn;
    }

    // --- write partial (fp32 O + l) ---
    float l0 = __shfl_sync(0xffffffffu, oacc[0][8][0], l & ~3);
    float l1 = __shfl_sync(0xffffffffu, oacc[0][8][2], l & ~3);
    float l2 = __shfl_sync(0xffffffffu, oacc[1][8][0], l & ~3);
    float l3 = __shfl_sync(0xffffffffu, oacc[1][8][2], l & ~3);
    {
        float* pO = g_pO + (size_t)sp*S_LEN*DM;
        #pragma unroll
        for (int rb = 0; rb < 2; rb++) {
            int rbase = q0 + w*32 + rb*16;
            #pragma unroll
            for (int j = 0; j < 8; j++) {
                *(float2*)&pO[(size_t)(rbase + g    )*DM + h*HD + j*8 + 2*q] =
                    make_float2(oacc[rb][j][0], oacc[rb][j][1]);
                *(float2*)&pO[(size_t)(rbase + g + 8)*DM + h*HD + j*8 + 2*q] =
                    make_float2(oacc[rb][j][2], oacc[rb][j][3]);
            }
        }
        if (q == 0) {
            float* pl = g_pl + (size_t)sp*S_LEN*NH;
            int rbase = q0 + w*32;
            pl[(size_t)(rbase + g     )*NH + h] = l0;
            pl[(size_t)(rbase + g +  8)*NH + h] = l1;
            pl[(size_t)(rbase + g + 16)*NH + h] = l2;
            pl[(size_t)(rbase + g + 24)*NH + h] = l3;
        }
    }
    __syncthreads();
    if (tid == 0) {
        __threadfence();
        s_last = atomicAdd(&g_ctr[blockIdx.x*NH + h], 1);
        __threadfence();
    }
    __syncthreads();
    if (s_last == 0) return;

    // --- second finisher: merge other split, normalize, write fp16 ---
    const int osp = 1 - sp;
    const float* oO = g_pO + (size_t)osp*S_LEN*DM;
    const float* ol = g_pl + (size_t)osp*S_LEN*NH;
    {
        int rbase = q0 + w*32;
        l0 += ol[(size_t)(rbase + g     )*NH + h];
        l1 += ol[(size_t)(rbase + g +  8)*NH + h];
        l2 += ol[(size_t)(rbase + g + 16)*NH + h];
        l3 += ol[(size_t)(rbase + g + 24)*NH + h];
    }
    float inv[2][2] = {{1.f/l0, 1.f/l1}, {1.f/l2, 1.f/l3}};
    #pragma unroll
    for (int rb = 0; rb < 2; rb++) {
        int rbase = q0 + w*32 + rb*16;
        #pragma unroll
        for (int j = 0; j < 8; j++) {
            float2 a = *(const float2*)&oO[(size_t)(rbase + g    )*DM + h*HD + j*8 + 2*q];
            float2 b = *(const float2*)&oO[(size_t)(rbase + g + 8)*DM + h*HD + j*8 + 2*q];
            out[(size_t)(rbase + g    )*(DM/2) + h*32 + 4*j + q] =
                h2pack((a.x + oacc[rb][j][0])*inv[rb][0], (a.y + oacc[rb][j][1])*inv[rb][0]);
            out[(size_t)(rbase + g + 8)*(DM/2) + h*32 + 4*j + q] =
                h2pack((b.x + oacc[rb][j][2])*inv[rb][1], (b.y + oacc[rb][j][3])*inv[rb][1]);
        }
    }
    #undef ISSUE
}

// ---------------------------------------------------------------------------
extern "C" void kernel_launch(void* const* d_in, const int* in_sizes, int n_in,
                              void* d_out, int out_size) {
    const float* x   = (const float*)d_in[0];
    const float* w_q = (const float*)d_in[1];
    const float* w_k = (const float*)d_in[2];
    const float* w_v = (const float*)d_in[3];
    const float* w_o = (const float*)d_in[4];
    float* out = (float*)d_out;

    uint32_t *x16, *ao16;
    cudaGetSymbolAddress((void**)&x16,  g_x16);
    cudaGetSymbolAddress((void**)&ao16, g_ao16);

    const int GEMM_SMEM = 3*GSTG*4;               // 73728 B
    const int ATTN_SMEM = 3*KVBLKW*4;             // 52224 B
    cudaFuncSetAttribute(gemm16_qkv, cudaFuncAttributeMaxDynamicSharedMemorySize, GEMM_SMEM);
    cudaFuncSetAttribute(gemm16_o,   cudaFuncAttributeMaxDynamicSharedMemorySize, GEMM_SMEM);
    cudaFuncSetAttribute(attn16,     cudaFuncAttributeMaxDynamicSharedMemorySize, ATTN_SMEM);

    // Conversion + semaphore reset
    {
        int total = S_LEN*DM/8 + 2*((DM/2)*(DM/4)) + 2*((DM/2)*(KV_W/4)) + (S_LEN/128)*NH;
        cvt_all<<<(total + 255)/256, 256>>>(x, w_q, w_k, w_v, w_o);
    }

    // Fused Q/K/V projections + RoPE + fp16 repack
    gemm16_qkv<<<dim3(24, S_LEN/256), 256, GEMM_SMEM>>>(x16);

    // Attention, split-KV x2
    attn16<<<dim3(S_LEN/128, NH, NSPLIT), 128, ATTN_SMEM>>>(ao16);

    // Output projection
    gemm16_o<<<dim3(DM/64, S_LEN/256), 256, GEMM_SMEM>>>(ao16, out);
}